// round 5
// baseline (speedup 1.0000x reference)
#include <cuda_runtime.h>
#include <cuda_bf16.h>
#include <cstdint>

// ConvSTFT via HMMA (mma.sync bf16) split-precision GEMM.
// C[f,q] = sum_n framed[f,n] * basisI[q,n]  per batch b
//   framed[f,n] = x[b, f*320 + n - 512]  (zero outside [0,160000))
//   basisI[q,n] = basis[(q>>1) + (q&1)*513, n]  (interleaved real/imag)
// Nonzero basis cols: n in [112,912) -> 13 chunks of 64 starting at 112.
// fp32 split: v = hi(bf16) + lo(bf16); C = Ah*Bh + Ah*Bl + Al*Bh  (3 passes).

#define TLEN    160000
#define NBATCH  32
#define FRAMES  501
#define NBINS   513
#define NFFT    1024
#define HOP     320
#define N0      112
#define NCH     13
#define TOTCH   (3 * NCH)      // 39 (chunk, pass) iterations
#define BM      128
#define BN      128
#define NSTAGE  3

#define STAGE_BYTES 32768      // A tile 16KB + B tile 16KB
#define SMEM_TOTAL  (NSTAGE * STAGE_BYTES)   // 96KB; epilogue reuses 64KB

// ---- scratch (device globals) ----
__device__ __align__(16) __nv_bfloat16 g_x_hi[(size_t)NBATCH * TLEN];
__device__ __align__(16) __nv_bfloat16 g_x_lo[(size_t)NBATCH * TLEN];
__device__ __align__(16) __nv_bfloat16 g_b_hi[(size_t)2 * NBINS * NFFT];
__device__ __align__(16) __nv_bfloat16 g_b_lo[(size_t)2 * NBINS * NFFT];

__device__ __forceinline__ uint32_t smem_u32(const void* p) {
    uint32_t a;
    asm("{ .reg .u64 t; cvta.to.shared.u64 t, %1; cvt.u32.u64 %0, t; }" : "=r"(a) : "l"(p));
    return a;
}
__device__ __forceinline__ uint32_t swz(uint32_t off) {   // SW128 xor swizzle
    return off ^ ((off >> 3) & 0x70);
}
__device__ __forceinline__ void cp16(uint32_t dst, const void* src, uint32_t sz) {
    asm volatile("cp.async.cg.shared.global [%0], [%1], 16, %2;"
                 :: "r"(dst), "l"(src), "r"(sz));
}
#define CP_COMMIT() asm volatile("cp.async.commit_group;" ::: "memory")
#define CP_WAIT(n)  asm volatile("cp.async.wait_group %0;" :: "n"(n) : "memory")

__device__ __forceinline__ void ldmx4(uint32_t* r, uint32_t addr) {
    asm volatile("ldmatrix.sync.aligned.m8n8.x4.shared.b16 {%0,%1,%2,%3}, [%4];"
                 : "=r"(r[0]), "=r"(r[1]), "=r"(r[2]), "=r"(r[3]) : "r"(addr));
}
__device__ __forceinline__ void mma16816(float* c, const uint32_t* a, const uint32_t* b) {
    asm volatile("mma.sync.aligned.m16n8k16.row.col.f32.bf16.bf16.f32 "
                 "{%0,%1,%2,%3}, {%4,%5,%6,%7}, {%8,%9}, {%0,%1,%2,%3};"
                 : "+f"(c[0]), "+f"(c[1]), "+f"(c[2]), "+f"(c[3])
                 : "r"(a[0]), "r"(a[1]), "r"(a[2]), "r"(a[3]), "r"(b[0]), "r"(b[1]));
}

// ---- pre-pass: fp32 -> (hi, lo) bf16, vectorized x4 ----
__global__ void convert_kernel(const float* __restrict__ x,
                               const float* __restrict__ basis) {
    const size_t NX = (size_t)NBATCH * TLEN;          // multiple of 4
    const size_t NB = (size_t)2 * NBINS * NFFT;       // multiple of 4
    size_t i4 = ((size_t)blockIdx.x * blockDim.x + threadIdx.x) * 4;
    if (i4 >= NX + NB) return;
    const float4 v = (i4 < NX) ? *(const float4*)(x + i4)
                               : *(const float4*)(basis + (i4 - NX));
    const float vv[4] = { v.x, v.y, v.z, v.w };
    union { ushort4 u; __nv_bfloat16 e[4]; } h, l;
#pragma unroll
    for (int e = 0; e < 4; e++) {
        __nv_bfloat16 hh = __float2bfloat16(vv[e]);
        h.e[e] = hh;
        l.e[e] = __float2bfloat16(vv[e] - __bfloat162float(hh));
    }
    if (i4 < NX) { *(ushort4*)(g_x_hi + i4) = h.u; *(ushort4*)(g_x_lo + i4) = l.u; }
    else { *(ushort4*)(g_b_hi + (i4 - NX)) = h.u; *(ushort4*)(g_b_lo + (i4 - NX)) = l.u; }
}

__global__ __launch_bounds__(512, 1)
void stft_hmma_kernel(float* __restrict__ out) {
    extern __shared__ __align__(16) char sm[];
    const uint32_t smb = smem_u32(sm);

    const int tid  = threadIdx.x;
    const int lane = tid & 31;
    const int wid  = tid >> 5;
    const int wm   = wid >> 2;          // warp M group (0-3): 32 frames
    const int wn   = wid & 3;           // warp N group (0-3): 32 bins

    const int f0 = blockIdx.x * BM;
    const int k0 = blockIdx.y * BN;
    const int b  = blockIdx.z;

    // ldmatrix lane address components
    const int aRow = wm * 32 + (lane & 15);
    const int aCol = ((lane >> 4) & 1) * 16;
    const int bRow = wn * 32 + (lane & 7) + ((lane >> 4) & 1) * 8;
    const int bCol = ((lane >> 3) & 1) * 16;

    float acc[2][4][4];
#pragma unroll
    for (int mi = 0; mi < 2; mi++)
#pragma unroll
        for (int ni = 0; ni < 4; ni++)
#pragma unroll
            for (int e = 0; e < 4; e++) acc[mi][ni][e] = 0.f;

    const size_t xb = (size_t)b * TLEN;

    // ---- chunk loader: (chunk cc, pass p) -> stage s ----
    auto load_chunk = [&](int c, int s) {
        const int p  = c / NCH;
        const int cc = c - p * NCH;
        const int kcol = N0 + cc * 64;
        const __nv_bfloat16* xsel = (p == 2) ? g_x_lo : g_x_hi;
        const __nv_bfloat16* bsel = (p == 1) ? g_b_lo : g_b_hi;
        const uint32_t stA = smb + s * STAGE_BYTES;
        const uint32_t stB = stA + 16384;
#pragma unroll
        for (int i = 0; i < 2; i++) {
            const int idx = tid + 512 * i;     // 0..1023
            const int r = idx >> 3;            // row 0..127
            const int u = idx & 7;             // 16B unit 0..7
            const uint32_t off = swz((uint32_t)(r * 128 + u * 16));
            // A (frames): xi0 always 8-aligned -> no boundary straddle
            const int xi0 = (f0 + r) * HOP + kcol + u * 8 - 512;
            const uint32_t szA = (xi0 >= 0 && xi0 + 8 <= TLEN) ? 16u : 0u;
            cp16(stA + off, xsel + xb + (xi0 < 0 ? 0 : xi0), szA);
            // B (interleaved bins)
            const int q = k0 + r;
            const int rowb = (q >> 1) + (q & 1) * NBINS;
            const uint32_t szB = (q < 2 * NBINS) ? 16u : 0u;
            cp16(stB + off, bsel + (size_t)(q < 2 * NBINS ? rowb : 0) * NFFT
                                 + kcol + u * 8, szB);
        }
        CP_COMMIT();
    };

    load_chunk(0, 0);
    load_chunk(1, 1);

    for (int c = 0; c < TOTCH; c++) {
        CP_WAIT(1);
        __syncthreads();

        // prefetch into the stage consumed at iteration c-1 (WAR-safe post-sync)
        if (c + 2 < TOTCH) load_chunk(c + 2, (c + 2) % NSTAGE);

        const uint32_t stA = smb + (c % NSTAGE) * STAGE_BYTES;
        const uint32_t stB = stA + 16384;

#pragma unroll
        for (int ks = 0; ks < 4; ks++) {
            uint32_t afr[2][4];
#pragma unroll
            for (int mi = 0; mi < 2; mi++)
                ldmx4(afr[mi], stA + swz((uint32_t)((aRow + mi * 16) * 128
                                                    + ks * 32 + aCol)));
            uint32_t bfr[4][2];
#pragma unroll
            for (int np = 0; np < 2; np++) {
                uint32_t r4[4];
                ldmx4(r4, stB + swz((uint32_t)((bRow + np * 16) * 128
                                               + ks * 32 + bCol)));
                bfr[np * 2][0]     = r4[0]; bfr[np * 2][1]     = r4[1];
                bfr[np * 2 + 1][0] = r4[2]; bfr[np * 2 + 1][1] = r4[3];
            }
#pragma unroll
            for (int mi = 0; mi < 2; mi++)
#pragma unroll
                for (int ni = 0; ni < 4; ni++)
                    mma16816(acc[mi][ni], afr[mi], bfr[ni]);
        }
    }

    // ---- epilogue: stage fp32 tile [q][f] in smem, then coalesced float2 out ----
    __syncthreads();
    float* ot = (float*)sm;       // 128 q rows x 128 f cols = 64KB
#pragma unroll
    for (int mi = 0; mi < 2; mi++)
#pragma unroll
        for (int ni = 0; ni < 4; ni++) {
            const int row = wm * 32 + mi * 16 + (lane >> 2);
            const int col = wn * 32 + ni * 8 + (lane & 3) * 2;
            ot[col * 128 + row]           = acc[mi][ni][0];
            ot[(col + 1) * 128 + row]     = acc[mi][ni][1];
            ot[col * 128 + row + 8]       = acc[mi][ni][2];
            ot[(col + 1) * 128 + row + 8] = acc[mi][ni][3];
        }
    __syncthreads();

#pragma unroll
    for (int i = 0; i < 16; i++) {
        const int idx = tid + 512 * i;   // 0..8191
        const int j = idx >> 7;          // bin pair 0..63
        const int f = idx & 127;
        const int q = k0 + 2 * j;
        const int ff = f0 + f;
        if (q < 2 * NBINS && ff < FRAMES) {
            const int kout = q >> 1;
            float2 v;
            v.x = ot[(2 * j) * 128 + f];
            v.y = ot[(2 * j + 1) * 128 + f];
            *(float2*)(out + (((size_t)b * NBINS + kout) * FRAMES + ff) * 2) = v;
        }
    }
}

extern "C" void kernel_launch(void* const* d_in, const int* in_sizes, int n_in,
                              void* d_out, int out_size) {
    const float* x     = (const float*)d_in[0];
    const float* basis = (const float*)d_in[1];
    float* out         = (float*)d_out;

    const size_t total4 = ((size_t)NBATCH * TLEN + (size_t)2 * NBINS * NFFT) / 4;
    convert_kernel<<<(unsigned)((total4 + 255) / 256), 256>>>(x, basis);

    cudaFuncSetAttribute(stft_hmma_kernel,
                         cudaFuncAttributeMaxDynamicSharedMemorySize, SMEM_TOTAL);
    dim3 grid((FRAMES + BM - 1) / BM,          // 4
              (2 * NBINS + BN - 1) / BN,       // 9
              NBATCH);                         // 32
    stft_hmma_kernel<<<grid, 512, SMEM_TOTAL>>>(out);
}

// round 6
// speedup vs baseline: 1.1851x; 1.1851x over previous
#include <cuda_runtime.h>
#include <cuda_bf16.h>
#include <cstdint>

// ConvSTFT via HMMA (mma.sync bf16) split-precision GEMM, fused passes.
// C[f,q] = sum_n framed[f,n] * basisI[q,n]  per batch b
//   framed[f,n] = x[b, f*320 + n - 512]  (zero outside [0,160000))
//   basisI[q,n] = basis[(q>>1) + (q&1)*513, n]  (interleaved real/imag)
// Nonzero basis cols: n in [112,912) -> 13 chunks of 64 starting at 112.
// fp32 split: v = hi + lo (bf16); C = Ah*Bh + Ah*Bl + Al*Bh.
// Per chunk load ONE set {Ah, Al, Bh, Bl} (64KB) and run all 3 passes on it.

#define TLEN    160000
#define NBATCH  32
#define FRAMES  501
#define NBINS   513
#define NFFT    1024
#define HOP     320
#define N0      112
#define NCH     13
#define BM      128
#define BN      128
#define NSTAGE  3

#define TILE_BYTES  16384
#define STAGE_BYTES (4 * TILE_BYTES)          // Ah | Al | Bh | Bl
#define SMEM_TOTAL  (NSTAGE * STAGE_BYTES)    // 192KB

// ---- scratch (device globals) ----
__device__ __align__(16) __nv_bfloat16 g_x_hi[(size_t)NBATCH * TLEN];
__device__ __align__(16) __nv_bfloat16 g_x_lo[(size_t)NBATCH * TLEN];
__device__ __align__(16) __nv_bfloat16 g_b_hi[(size_t)2 * NBINS * NFFT];
__device__ __align__(16) __nv_bfloat16 g_b_lo[(size_t)2 * NBINS * NFFT];

__device__ __forceinline__ uint32_t smem_u32(const void* p) {
    uint32_t a;
    asm("{ .reg .u64 t; cvta.to.shared.u64 t, %1; cvt.u32.u64 %0, t; }" : "=r"(a) : "l"(p));
    return a;
}
__device__ __forceinline__ uint32_t swz(uint32_t off) {   // SW128 xor swizzle
    return off ^ ((off >> 3) & 0x70);
}
__device__ __forceinline__ void cp16(uint32_t dst, const void* src, uint32_t sz) {
    asm volatile("cp.async.cg.shared.global [%0], [%1], 16, %2;"
                 :: "r"(dst), "l"(src), "r"(sz));
}
#define CP_COMMIT() asm volatile("cp.async.commit_group;" ::: "memory")
#define CP_WAIT(n)  asm volatile("cp.async.wait_group %0;" :: "n"(n) : "memory")

__device__ __forceinline__ void ldmx4(uint32_t* r, uint32_t addr) {
    asm volatile("ldmatrix.sync.aligned.m8n8.x4.shared.b16 {%0,%1,%2,%3}, [%4];"
                 : "=r"(r[0]), "=r"(r[1]), "=r"(r[2]), "=r"(r[3]) : "r"(addr));
}
__device__ __forceinline__ void mma16816(float* c, const uint32_t* a, const uint32_t* b) {
    asm volatile("mma.sync.aligned.m16n8k16.row.col.f32.bf16.bf16.f32 "
                 "{%0,%1,%2,%3}, {%4,%5,%6,%7}, {%8,%9}, {%0,%1,%2,%3};"
                 : "+f"(c[0]), "+f"(c[1]), "+f"(c[2]), "+f"(c[3])
                 : "r"(a[0]), "r"(a[1]), "r"(a[2]), "r"(a[3]), "r"(b[0]), "r"(b[1]));
}

// ---- pre-pass: fp32 -> (hi, lo) bf16, vectorized x4 ----
__global__ void convert_kernel(const float* __restrict__ x,
                               const float* __restrict__ basis) {
    const size_t NX = (size_t)NBATCH * TLEN;
    const size_t NB = (size_t)2 * NBINS * NFFT;
    size_t i4 = ((size_t)blockIdx.x * blockDim.x + threadIdx.x) * 4;
    if (i4 >= NX + NB) return;
    const float4 v = (i4 < NX) ? *(const float4*)(x + i4)
                               : *(const float4*)(basis + (i4 - NX));
    const float vv[4] = { v.x, v.y, v.z, v.w };
    union { ushort4 u; __nv_bfloat16 e[4]; } h, l;
#pragma unroll
    for (int e = 0; e < 4; e++) {
        __nv_bfloat16 hh = __float2bfloat16(vv[e]);
        h.e[e] = hh;
        l.e[e] = __float2bfloat16(vv[e] - __bfloat162float(hh));
    }
    if (i4 < NX) { *(ushort4*)(g_x_hi + i4) = h.u; *(ushort4*)(g_x_lo + i4) = l.u; }
    else { *(ushort4*)(g_b_hi + (i4 - NX)) = h.u; *(ushort4*)(g_b_lo + (i4 - NX)) = l.u; }
}

__global__ __launch_bounds__(512, 1)
void stft_hmma_kernel(float* __restrict__ out) {
    extern __shared__ __align__(16) char sm[];
    const uint32_t smb = smem_u32(sm);

    const int tid  = threadIdx.x;
    const int lane = tid & 31;
    const int wid  = tid >> 5;
    const int wm   = wid >> 2;          // warp M group (0-3): 32 frames
    const int wn   = wid & 3;           // warp N group (0-3): 32 bins

    const int f0 = blockIdx.x * BM;
    const int k0 = blockIdx.y * BN;
    const int b  = blockIdx.z;

    // ldmatrix lane address components
    const int aRow = wm * 32 + (lane & 15);
    const int aCol = ((lane >> 4) & 1) * 16;
    const int bRow = wn * 32 + (lane & 7) + ((lane >> 4) & 1) * 8;
    const int bCol = ((lane >> 3) & 1) * 16;

    float acc[2][4][4];
#pragma unroll
    for (int mi = 0; mi < 2; mi++)
#pragma unroll
        for (int ni = 0; ni < 4; ni++)
#pragma unroll
            for (int e = 0; e < 4; e++) acc[mi][ni][e] = 0.f;

    const size_t xb = (size_t)b * TLEN;

    // ---- chunk loader: load {Ah, Al, Bh, Bl} for chunk cc into stage s ----
    auto load_chunk = [&](int cc, int s) {
        const int kcol = N0 + cc * 64;
        const uint32_t st = smb + s * STAGE_BYTES;
#pragma unroll
        for (int j = 0; j < 8; j++) {
            const int idx  = tid + 512 * j;       // 0..4095
            const int u    = idx & 7;             // 16B unit
            const int r    = (idx >> 3) & 127;    // row
            const int tile = idx >> 10;           // 0:Ah 1:Al 2:Bh 3:Bl
            const uint32_t dst = st + tile * TILE_BYTES
                               + swz((uint32_t)(r * 128 + u * 16));
            if (tile < 2) {            // A (frames); xi0 8-aligned, no straddle
                const __nv_bfloat16* src = (tile == 0) ? g_x_hi : g_x_lo;
                const int xi0 = (f0 + r) * HOP + kcol + u * 8 - 512;
                const uint32_t sz = (xi0 >= 0 && xi0 + 8 <= TLEN) ? 16u : 0u;
                cp16(dst, src + xb + (xi0 < 0 ? 0 : xi0), sz);
            } else {                   // B (interleaved bins)
                const __nv_bfloat16* src = (tile == 2) ? g_b_hi : g_b_lo;
                const int q = k0 + r;
                const int rowb = (q >> 1) + (q & 1) * NBINS;
                const uint32_t sz = (q < 2 * NBINS) ? 16u : 0u;
                cp16(dst, src + (size_t)(q < 2 * NBINS ? rowb : 0) * NFFT
                              + kcol + u * 8, sz);
            }
        }
        CP_COMMIT();
    };

    load_chunk(0, 0);
    load_chunk(1, 1);

    for (int c = 0; c < NCH; c++) {
        CP_WAIT(1);
        __syncthreads();

        // prefetch into the stage consumed at iteration c-1 (WAR-safe post-sync)
        if (c + 2 < NCH) load_chunk(c + 2, (c + 2) % NSTAGE);

        const uint32_t st = smb + (c % NSTAGE) * STAGE_BYTES;

        // 3 passes on one resident chunk: (Ah,Bh), (Ah,Bl), (Al,Bh)
#pragma unroll
        for (int pp = 0; pp < 3; pp++) {
            const uint32_t stA = st + ((pp == 2) ? TILE_BYTES : 0);
            const uint32_t stB = st + 2 * TILE_BYTES + ((pp == 1) ? TILE_BYTES : 0);
#pragma unroll
            for (int ks = 0; ks < 4; ks++) {
                uint32_t afr[2][4];
#pragma unroll
                for (int mi = 0; mi < 2; mi++)
                    ldmx4(afr[mi], stA + swz((uint32_t)((aRow + mi * 16) * 128
                                                        + ks * 32 + aCol)));
                uint32_t bfr[4][2];
#pragma unroll
                for (int np = 0; np < 2; np++) {
                    uint32_t r4[4];
                    ldmx4(r4, stB + swz((uint32_t)((bRow + np * 16) * 128
                                                   + ks * 32 + bCol)));
                    bfr[np * 2][0]     = r4[0]; bfr[np * 2][1]     = r4[1];
                    bfr[np * 2 + 1][0] = r4[2]; bfr[np * 2 + 1][1] = r4[3];
                }
#pragma unroll
                for (int mi = 0; mi < 2; mi++)
#pragma unroll
                    for (int ni = 0; ni < 4; ni++)
                        mma16816(acc[mi][ni], afr[mi], bfr[ni]);
            }
        }
    }

    // ---- epilogue: stage fp32 tile [q][f] in smem, then coalesced float2 out ----
    __syncthreads();
    float* ot = (float*)sm;       // 128 q rows x 128 f cols = 64KB
#pragma unroll
    for (int mi = 0; mi < 2; mi++)
#pragma unroll
        for (int ni = 0; ni < 4; ni++) {
            const int row = wm * 32 + mi * 16 + (lane >> 2);
            const int col = wn * 32 + ni * 8 + (lane & 3) * 2;
            ot[col * 128 + row]           = acc[mi][ni][0];
            ot[(col + 1) * 128 + row]     = acc[mi][ni][1];
            ot[col * 128 + row + 8]       = acc[mi][ni][2];
            ot[(col + 1) * 128 + row + 8] = acc[mi][ni][3];
        }
    __syncthreads();

#pragma unroll
    for (int i = 0; i < 16; i++) {
        const int idx = tid + 512 * i;   // 0..8191
        const int j = idx >> 7;          // bin pair 0..63
        const int f = idx & 127;
        const int q = k0 + 2 * j;
        const int ff = f0 + f;
        if (q < 2 * NBINS && ff < FRAMES) {
            const int kout = q >> 1;
            float2 v;
            v.x = ot[(2 * j) * 128 + f];
            v.y = ot[(2 * j + 1) * 128 + f];
            *(float2*)(out + (((size_t)b * NBINS + kout) * FRAMES + ff) * 2) = v;
        }
    }
}

extern "C" void kernel_launch(void* const* d_in, const int* in_sizes, int n_in,
                              void* d_out, int out_size) {
    const float* x     = (const float*)d_in[0];
    const float* basis = (const float*)d_in[1];
    float* out         = (float*)d_out;

    const size_t total4 = ((size_t)NBATCH * TLEN + (size_t)2 * NBINS * NFFT) / 4;
    convert_kernel<<<(unsigned)((total4 + 255) / 256), 256>>>(x, basis);

    cudaFuncSetAttribute(stft_hmma_kernel,
                         cudaFuncAttributeMaxDynamicSharedMemorySize, SMEM_TOTAL);
    dim3 grid((FRAMES + BM - 1) / BM,          // 4
              (2 * NBINS + BN - 1) / BN,       // 9
              NBATCH);                         // 32
    stft_hmma_kernel<<<grid, 512, SMEM_TOTAL>>>(out);
}

// round 7
// speedup vs baseline: 1.2734x; 1.0744x over previous
#include <cuda_runtime.h>
#include <cuda_bf16.h>
#include <cstdint>

// ConvSTFT via HMMA (mma.sync bf16) split-precision GEMM, fully fused passes.
// C[f,q] = sum_n framed[f,n] * basisI[q,n]  per batch b
//   framed[f,n] = x[b, f*320 + n - 512]  (zero outside [0,160000))
//   basisI[q,n] = basis[(q>>1) + (q&1)*513, n]  (interleaved real/imag)
// Nonzero basis cols: n in [112,912) -> 13 chunks of 64 starting at 112.
// fp32 split: v = hi + lo (bf16); C = Ah*Bh + Ah*Bl + Al*Bh.
// Per chunk load ONE set {Ah, Al, Bh, Bl}; per ks-step load operand fragments
// once (Ah, Bh, Bl; then Al overwrites Ah) -> 8 ldmx4 / 24 HMMA per ks.

#define TLEN    160000
#define NBATCH  32
#define FRAMES  501
#define NBINS   513
#define QTOT    1026
#define NFFT    1024
#define HOP     320
#define N0      112
#define NCH     13
#define BM      128
#define BN      128
#define NSTAGE  3

#define TILE_BYTES  16384
#define STAGE_BYTES (4 * TILE_BYTES)          // Ah | Al | Bh | Bl
#define SMEM_TOTAL  (NSTAGE * STAGE_BYTES)    // 192KB

// ---- scratch (device globals) ----
__device__ __align__(16) __nv_bfloat16 g_x_hi[(size_t)NBATCH * TLEN];
__device__ __align__(16) __nv_bfloat16 g_x_lo[(size_t)NBATCH * TLEN];
__device__ __align__(16) __nv_bfloat16 g_b_hi[(size_t)2 * NBINS * NFFT];
__device__ __align__(16) __nv_bfloat16 g_b_lo[(size_t)2 * NBINS * NFFT];

__device__ __forceinline__ uint32_t smem_u32(const void* p) {
    uint32_t a;
    asm("{ .reg .u64 t; cvta.to.shared.u64 t, %1; cvt.u32.u64 %0, t; }" : "=r"(a) : "l"(p));
    return a;
}
__device__ __forceinline__ uint32_t swz(uint32_t off) {   // SW128 xor swizzle
    return off ^ ((off >> 3) & 0x70);
}
__device__ __forceinline__ void cp16(uint32_t dst, const void* src, uint32_t sz) {
    asm volatile("cp.async.cg.shared.global [%0], [%1], 16, %2;"
                 :: "r"(dst), "l"(src), "r"(sz));
}
#define CP_COMMIT() asm volatile("cp.async.commit_group;" ::: "memory")
#define CP_WAIT(n)  asm volatile("cp.async.wait_group %0;" :: "n"(n) : "memory")

__device__ __forceinline__ void ldmx4(uint32_t* r, uint32_t addr) {
    asm volatile("ldmatrix.sync.aligned.m8n8.x4.shared.b16 {%0,%1,%2,%3}, [%4];"
                 : "=r"(r[0]), "=r"(r[1]), "=r"(r[2]), "=r"(r[3]) : "r"(addr));
}
__device__ __forceinline__ void mma16816(float* c, const uint32_t* a, const uint32_t* b) {
    asm volatile("mma.sync.aligned.m16n8k16.row.col.f32.bf16.bf16.f32 "
                 "{%0,%1,%2,%3}, {%4,%5,%6,%7}, {%8,%9}, {%0,%1,%2,%3};"
                 : "+f"(c[0]), "+f"(c[1]), "+f"(c[2]), "+f"(c[3])
                 : "r"(a[0]), "r"(a[1]), "r"(a[2]), "r"(a[3]), "r"(b[0]), "r"(b[1]));
}

// ---- pre-pass: fp32 -> (hi, lo) bf16, vectorized x4 ----
__global__ void convert_kernel(const float* __restrict__ x,
                               const float* __restrict__ basis) {
    const size_t NX = (size_t)NBATCH * TLEN;
    const size_t NB = (size_t)2 * NBINS * NFFT;
    size_t i4 = ((size_t)blockIdx.x * blockDim.x + threadIdx.x) * 4;
    if (i4 >= NX + NB) return;
    const float4 v = (i4 < NX) ? *(const float4*)(x + i4)
                               : *(const float4*)(basis + (i4 - NX));
    const float vv[4] = { v.x, v.y, v.z, v.w };
    union { ushort4 u; __nv_bfloat16 e[4]; } h, l;
#pragma unroll
    for (int e = 0; e < 4; e++) {
        __nv_bfloat16 hh = __float2bfloat16(vv[e]);
        h.e[e] = hh;
        l.e[e] = __float2bfloat16(vv[e] - __bfloat162float(hh));
    }
    if (i4 < NX) { *(ushort4*)(g_x_hi + i4) = h.u; *(ushort4*)(g_x_lo + i4) = l.u; }
    else { *(ushort4*)(g_b_hi + (i4 - NX)) = h.u; *(ushort4*)(g_b_lo + (i4 - NX)) = l.u; }
}

__global__ __launch_bounds__(512, 1)
void stft_hmma_kernel(float* __restrict__ out) {
    extern __shared__ __align__(16) char sm[];
    const uint32_t smb = smem_u32(sm);

    const int tid  = threadIdx.x;
    const int lane = tid & 31;
    const int wid  = tid >> 5;
    const int wm   = wid >> 2;          // warp M group (0-3): 32 frames
    const int wn   = wid & 3;           // warp N group (0-3): 32 bins

    const int f0 = blockIdx.x * BM;
    const int k0 = blockIdx.y * BN;
    const int b  = blockIdx.z;

    // valid n8 fragments for this warp (tile 8 has only 2 valid bins)
    const int rem   = QTOT - (k0 + wn * 32);
    const int niMax = rem >= 32 ? 4 : (rem <= 0 ? 0 : ((rem + 7) >> 3));
    const int npMax = (niMax + 1) >> 1;

    // ldmatrix lane address components
    const int aRow = wm * 32 + (lane & 15);
    const int aCol = ((lane >> 4) & 1) * 16;
    const int bRow = wn * 32 + (lane & 7) + ((lane >> 4) & 1) * 8;
    const int bCol = ((lane >> 3) & 1) * 16;

    float acc[2][4][4];
#pragma unroll
    for (int mi = 0; mi < 2; mi++)
#pragma unroll
        for (int ni = 0; ni < 4; ni++)
#pragma unroll
            for (int e = 0; e < 4; e++) acc[mi][ni][e] = 0.f;

    const size_t xb = (size_t)b * TLEN;

    // ---- chunk loader: load {Ah, Al, Bh, Bl} for chunk cc into stage s ----
    auto load_chunk = [&](int cc, int s) {
        const int kcol = N0 + cc * 64;
        const uint32_t st = smb + s * STAGE_BYTES;
#pragma unroll
        for (int j = 0; j < 8; j++) {
            const int idx  = tid + 512 * j;       // 0..4095
            const int u    = idx & 7;             // 16B unit
            const int r    = (idx >> 3) & 127;    // row
            const int tile = idx >> 10;           // 0:Ah 1:Al 2:Bh 3:Bl
            const uint32_t dst = st + tile * TILE_BYTES
                               + swz((uint32_t)(r * 128 + u * 16));
            if (tile < 2) {            // A (frames); xi0 8-aligned, no straddle
                const __nv_bfloat16* src = (tile == 0) ? g_x_hi : g_x_lo;
                const int xi0 = (f0 + r) * HOP + kcol + u * 8 - 512;
                const uint32_t sz = (xi0 >= 0 && xi0 + 8 <= TLEN) ? 16u : 0u;
                cp16(dst, src + xb + (xi0 < 0 ? 0 : xi0), sz);
            } else {                   // B (interleaved bins)
                const __nv_bfloat16* src = (tile == 2) ? g_b_hi : g_b_lo;
                const int q = k0 + r;
                const int rowb = (q >> 1) + (q & 1) * NBINS;
                const uint32_t sz = (q < QTOT) ? 16u : 0u;
                cp16(dst, src + (size_t)(q < QTOT ? rowb : 0) * NFFT
                              + kcol + u * 8, sz);
            }
        }
        CP_COMMIT();
    };

    load_chunk(0, 0);
    load_chunk(1, 1);

    for (int c = 0; c < NCH; c++) {
        CP_WAIT(1);
        __syncthreads();

        // prefetch into the stage consumed at iteration c-1 (WAR-safe post-sync)
        if (c + 2 < NCH) load_chunk(c + 2, (c + 2) % NSTAGE);

        const uint32_t st   = smb + (c % NSTAGE) * STAGE_BYTES;
        const uint32_t stAh = st;
        const uint32_t stAl = st + TILE_BYTES;
        const uint32_t stBh = st + 2 * TILE_BYTES;
        const uint32_t stBl = st + 3 * TILE_BYTES;

#pragma unroll
        for (int ks = 0; ks < 4; ks++) {
            const uint32_t aOff = swz((uint32_t)(aRow * 128 + ks * 32 + aCol));
            const uint32_t aOff1 = swz((uint32_t)((aRow + 16) * 128 + ks * 32 + aCol));
            const uint32_t bOff[2] = {
                swz((uint32_t)(bRow * 128 + ks * 32 + bCol)),
                swz((uint32_t)((bRow + 16) * 128 + ks * 32 + bCol)) };

            uint32_t afr[2][4], bfrH[4][2], bfrL[4][2];

            // A-hi fragments
            ldmx4(afr[0], stAh + aOff);
            ldmx4(afr[1], stAh + aOff1);
            // B-hi fragments (guarded; zero fragments skipped)
#pragma unroll
            for (int np = 0; np < 2; np++)
                if (np < npMax) {
                    uint32_t r4[4];
                    ldmx4(r4, stBh + bOff[np]);
                    bfrH[np * 2][0]     = r4[0]; bfrH[np * 2][1]     = r4[1];
                    bfrH[np * 2 + 1][0] = r4[2]; bfrH[np * 2 + 1][1] = r4[3];
                }
            // Ah * Bh
#pragma unroll
            for (int mi = 0; mi < 2; mi++)
#pragma unroll
                for (int ni = 0; ni < 4; ni++)
                    if (ni < niMax) mma16816(acc[mi][ni], afr[mi], bfrH[ni]);

            // B-lo fragments
#pragma unroll
            for (int np = 0; np < 2; np++)
                if (np < npMax) {
                    uint32_t r4[4];
                    ldmx4(r4, stBl + bOff[np]);
                    bfrL[np * 2][0]     = r4[0]; bfrL[np * 2][1]     = r4[1];
                    bfrL[np * 2 + 1][0] = r4[2]; bfrL[np * 2 + 1][1] = r4[3];
                }
            // Ah * Bl
#pragma unroll
            for (int mi = 0; mi < 2; mi++)
#pragma unroll
                for (int ni = 0; ni < 4; ni++)
                    if (ni < niMax) mma16816(acc[mi][ni], afr[mi], bfrL[ni]);

            // A-lo overwrites A-hi
            ldmx4(afr[0], stAl + aOff);
            ldmx4(afr[1], stAl + aOff1);
            // Al * Bh
#pragma unroll
            for (int mi = 0; mi < 2; mi++)
#pragma unroll
                for (int ni = 0; ni < 4; ni++)
                    if (ni < niMax) mma16816(acc[mi][ni], afr[mi], bfrH[ni]);
        }
    }

    // ---- epilogue: stage fp32 tile [q][f] in smem, then coalesced float2 out ----
    __syncthreads();
    float* ot = (float*)sm;       // 128 q rows x 128 f cols = 64KB
#pragma unroll
    for (int mi = 0; mi < 2; mi++)
#pragma unroll
        for (int ni = 0; ni < 4; ni++) {
            const int row = wm * 32 + mi * 16 + (lane >> 2);
            const int col = wn * 32 + ni * 8 + (lane & 3) * 2;
            ot[col * 128 + row]           = acc[mi][ni][0];
            ot[(col + 1) * 128 + row]     = acc[mi][ni][1];
            ot[col * 128 + row + 8]       = acc[mi][ni][2];
            ot[(col + 1) * 128 + row + 8] = acc[mi][ni][3];
        }
    __syncthreads();

#pragma unroll
    for (int i = 0; i < 16; i++) {
        const int idx = tid + 512 * i;   // 0..8191
        const int j = idx >> 7;          // bin pair 0..63
        const int f = idx & 127;
        const int q = k0 + 2 * j;
        const int ff = f0 + f;
        if (q < QTOT && ff < FRAMES) {
            const int kout = q >> 1;
            float2 v;
            v.x = ot[(2 * j) * 128 + f];
            v.y = ot[(2 * j + 1) * 128 + f];
            *(float2*)(out + (((size_t)b * NBINS + kout) * FRAMES + ff) * 2) = v;
        }
    }
}

extern "C" void kernel_launch(void* const* d_in, const int* in_sizes, int n_in,
                              void* d_out, int out_size) {
    const float* x     = (const float*)d_in[0];
    const float* basis = (const float*)d_in[1];
    float* out         = (float*)d_out;

    const size_t total4 = ((size_t)NBATCH * TLEN + (size_t)2 * NBINS * NFFT) / 4;
    convert_kernel<<<(unsigned)((total4 + 255) / 256), 256>>>(x, basis);

    cudaFuncSetAttribute(stft_hmma_kernel,
                         cudaFuncAttributeMaxDynamicSharedMemorySize, SMEM_TOTAL);
    dim3 grid((FRAMES + BM - 1) / BM,          // 4
              (QTOT + BN - 1) / BN,            // 9
              NBATCH);                         // 32
    stft_hmma_kernel<<<grid, 512, SMEM_TOTAL>>>(out);
}

// round 8
// speedup vs baseline: 3.2378x; 2.5427x over previous
#include <cuda_runtime.h>
#include <cstdint>
#include <math.h>

// ConvSTFT via windowed radix-4 Stockham FFT (N=1024), one frame per
// 128-thread group, 4 frames per 512-thread CTA.
//   out[b,k,f,:] = (Re,Im) of sum_t framed[t] * e^{-2*pi*i*k*t/1024}
//   framed[t] = x[b, f*320 + t - 512] * win[t]   (zero-padded)
// Matches reference: cos(ang) and -sin(ang) == forward DFT convention.

#define TLEN   160000
#define NBATCH 32
#define FRAMES 501
#define NBINS  513
#define HOP    320
#define NFFT   1024
#define FG     4
#define PADN   1088            // au(1023) = 1086

__device__ float  g_win[NFFT];
__device__ float2 g_twid[256];  // e^{-2*pi*i*t/1024}, t < 256

__global__ void table_kernel() {
    const int t = threadIdx.x;
    for (int p = t; p < NFFT; p += 256) {
        double w = 0.0;
        if (p >= 112 && p < 912) {
            double nn = (double)(p - 112);
            w = 0.5 * (1.0 - cos(2.0 * M_PI * nn / 799.0));
        }
        g_win[p] = (float)w;
    }
    if (t < 256) {
        double ang = 2.0 * M_PI * (double)t / 1024.0;
        g_twid[t] = make_float2((float)cos(ang), (float)(-sin(ang)));
    }
}

__device__ __forceinline__ int au(int u) { return u + (u >> 4); }  // bank pad
__device__ __forceinline__ float2 cadd(float2 a, float2 b) {
    return make_float2(a.x + b.x, a.y + b.y);
}
__device__ __forceinline__ float2 csub(float2 a, float2 b) {
    return make_float2(a.x - b.x, a.y - b.y);
}
__device__ __forceinline__ float2 cmul(float2 a, float2 b) {
    return make_float2(a.x * b.x - a.y * b.y, a.x * b.y + a.y * b.x);
}

__global__ __launch_bounds__(512, 3)
void stft_fft_kernel(const float* __restrict__ x, float* __restrict__ out) {
    extern __shared__ __align__(16) float2 smem[];
    // layout: [FG][2][PADN] ping-pong buffers, then twiddle[256]
    float2* stw = smem + FG * 2 * PADN;

    const int tid = threadIdx.x;
    const int g   = tid >> 7;       // frame group 0..3
    const int gt  = tid & 127;      // thread within group
    const int f0  = blockIdx.x * FG;
    const int b   = blockIdx.y;
    const int f   = f0 + g;

    float2* buf0 = smem + g * 2 * PADN;
    float2* buf1 = buf0 + PADN;

    if (tid < 256) stw[tid] = g_twid[tid];

    // ---- load + window ----
    const float* xb = x + (size_t)b * TLEN;
#pragma unroll
    for (int j = 0; j < 8; j++) {
        const int p  = gt + 128 * j;
        const int xi = f * HOP + p - 512;
        float v = 0.f;
        if (f < FRAMES && xi >= 0 && xi < TLEN) v = xb[xi] * g_win[p];
        buf0[au(p)] = make_float2(v, 0.f);
    }
    __syncthreads();

    // ---- radix-4 Stockham, 5 stages ----
    int cb = 0;
#pragma unroll
    for (int st = 0; st < 5; st++) {
        const int s = 1 << (2 * st);          // 1,4,16,64,256
        float2* cur = cb ? buf1 : buf0;
        float2* nxt = cb ? buf0 : buf1;
#pragma unroll
        for (int r = 0; r < 2; r++) {
            const int idx = gt + 128 * r;     // 0..255
            const int ps  = idx & ~(s - 1);   // p*s  (twiddle index)
            const float2 a0 = cur[au(idx)];
            const float2 a1 = cur[au(idx + 256)];
            const float2 a2 = cur[au(idx + 512)];
            const float2 a3 = cur[au(idx + 768)];
            const float2 b0 = cadd(a0, a2);
            const float2 b1 = cadd(a1, a3);
            const float2 b2 = csub(a0, a2);
            const float2 d  = csub(a1, a3);
            const float2 b3 = make_float2(d.y, -d.x);   // -i * d
            const float2 w1 = stw[ps];
            const float2 w2 = cmul(w1, w1);
            const float2 w3 = cmul(w1, w2);
            const int wi = idx + 3 * ps;
            nxt[au(wi)]         = cadd(b0, b1);
            nxt[au(wi + s)]     = cmul(cadd(b2, b3), w1);
            nxt[au(wi + 2 * s)] = cmul(csub(b0, b1), w2);
            nxt[au(wi + 3 * s)] = cmul(csub(b2, b3), w3);
        }
        cb ^= 1;
        __syncthreads();
    }
    // result in buf1 of each group (cb ended at 1)

    // ---- output: per bin k, write 4 consecutive frames (32B contiguous) ----
    float2* o2 = (float2*)out;
    for (int k = tid; k < NBINS; k += 512) {
        const size_t base = ((size_t)b * NBINS + k) * FRAMES + f0;
#pragma unroll
        for (int gg = 0; gg < FG; gg++) {
            if (f0 + gg < FRAMES) {
                const float2* rb = smem + gg * 2 * PADN + PADN;  // group gg buf1
                o2[base + gg] = rb[au(k)];
            }
        }
    }
}

extern "C" void kernel_launch(void* const* d_in, const int* in_sizes, int n_in,
                              void* d_out, int out_size) {
    const float* x = (const float*)d_in[0];
    float* out     = (float*)d_out;

    table_kernel<<<1, 256>>>();

    const int smem_bytes = (FG * 2 * PADN + 256) * sizeof(float2);  // 71680
    cudaFuncSetAttribute(stft_fft_kernel,
                         cudaFuncAttributeMaxDynamicSharedMemorySize, smem_bytes);
    dim3 grid((FRAMES + FG - 1) / FG,   // 126
              NBATCH);                  // 32
    stft_fft_kernel<<<grid, 512, smem_bytes>>>(x, out);
}

// round 9
// speedup vs baseline: 5.1250x; 1.5829x over previous
#include <cuda_runtime.h>
#include <cstdint>
#include <math.h>

// ConvSTFT via windowed FFT-1024 = 16 x 16 x 4 (four-step), register radix-16.
//   out[b,k,f,:] = (Re,Im) of sum_t x[b,f*320+t-512]*win[t]*e^{-2pi i k t/1024}
// Stage A: FFT-16 over n1 (stride 64) in regs, twiddle W1024^{k1*n2}, smem.
// Stage B: FFT-16 over m1 (stride 4 in n2) in regs, twiddle W64^{j1*m2}, smem.
// Stage C: radix-4 over m2; bin k = k1 + 16*j1 + 256*j2. Only k<=512 stored.

#define TLEN   160000
#define NBATCH 32
#define FRAMES 501
#define NBINS  513
#define HOP    320
#define FG     4                 // frames per CTA (64 threads each)

__device__ float  g_win[1024];
__device__ float2 g_tw64[64];    // W_1024^e, e < 64

__global__ void table_kernel() {
    int id = blockIdx.x * 64 + threadIdx.x;
    if (id < 1024) {
        double w = 0.0;
        if (id >= 112 && id < 912)
            w = 0.5 * (1.0 - cos(2.0 * M_PI * (double)(id - 112) / 799.0));
        g_win[id] = (float)w;
    } else if (id < 1088) {
        int e = id - 1024;
        double ang = 2.0 * M_PI * (double)e / 1024.0;
        g_tw64[e] = make_float2((float)cos(ang), (float)(-sin(ang)));
    }
}

__device__ __forceinline__ float2 cadd(float2 a, float2 b) {
    return make_float2(a.x + b.x, a.y + b.y);
}
__device__ __forceinline__ float2 csub(float2 a, float2 b) {
    return make_float2(a.x - b.x, a.y - b.y);
}
__device__ __forceinline__ float2 cmul(float2 a, float2 b) {
    return make_float2(a.x * b.x - a.y * b.y, a.x * b.y + a.y * b.x);
}
// radix-4 DFT: a..d <- X[0..3]; X1 = t1 - i*t3, X3 = t1 + i*t3
__device__ __forceinline__ void r4(float2& a, float2& b, float2& c, float2& d) {
    float2 t0 = cadd(a, c), t1 = csub(a, c), t2 = cadd(b, d), t3 = csub(b, d);
    a = cadd(t0, t2);
    b = make_float2(t1.x + t3.y, t1.y - t3.x);
    c = csub(t0, t2);
    d = make_float2(t1.x - t3.y, t1.y + t3.x);
}
// FFT-16 in regs. Output: slot s = 4*k1+k2 holds freq (k1 + 4*k2);
// i.e. freq f lives at slot perm(f) = ((f&3)<<2) | (f>>2).
__device__ __forceinline__ void fft16(float2 v[16]) {
#pragma unroll
    for (int n2 = 0; n2 < 4; n2++) r4(v[n2], v[n2 + 4], v[n2 + 8], v[n2 + 12]);
    const float C8 = 0.70710678118654752f;
    const float c1 = 0.92387953251128674f, s1 = 0.38268343236508977f;
    const float2 W1 = make_float2(c1, -s1),  W2 = make_float2(C8, -C8);
    const float2 W3 = make_float2(s1, -c1),  W4 = make_float2(0.f, -1.f);
    const float2 W6 = make_float2(-C8, -C8), W9 = make_float2(-c1, s1);
    v[5]  = cmul(v[5],  W1); v[6]  = cmul(v[6],  W2); v[7]  = cmul(v[7],  W3);
    v[9]  = cmul(v[9],  W2); v[10] = cmul(v[10], W4); v[11] = cmul(v[11], W6);
    v[13] = cmul(v[13], W3); v[14] = cmul(v[14], W6); v[15] = cmul(v[15], W9);
#pragma unroll
    for (int k1 = 0; k1 < 4; k1++) r4(v[4*k1], v[4*k1+1], v[4*k1+2], v[4*k1+3]);
}

__global__ __launch_bounds__(256)
void stft_fft_kernel(const float* __restrict__ x, float* __restrict__ out) {
    extern __shared__ float smem[];   // [FG][re 1088 | im 1088]
    const int tid = threadIdx.x;
    const int g   = tid >> 6;         // frame within CTA
    const int u   = tid & 63;         // thread within frame (= n2)
    const int f   = blockIdx.x * FG + g;
    const int b   = blockIdx.y;
    float* SRe = smem + g * 2176;
    float* SIm = SRe + 1088;
    const bool fv = (f < FRAMES);
    const float* xb = x + (size_t)b * TLEN;

    // ---- stage A: load+window, FFT-16 over n1 (stride 64) ----
    float2 v[16];
#pragma unroll
    for (int n1 = 0; n1 < 16; n1++) {
        const int p  = n1 * 64 + u;
        const int xi = f * HOP + p - 512;
        float val = 0.f;
        if (fv && xi >= 0 && xi < TLEN) val = xb[xi] * g_win[p];
        v[n1] = make_float2(val, 0.f);
    }
    fft16(v);
    {   // twiddle W_1024^{k1*u} (iterated powers), write S1[k1*68 + u]
        const float2 w = g_tw64[u];
        float2 t = w;
        SRe[u] = v[0].x; SIm[u] = v[0].y;
#pragma unroll
        for (int k1 = 1; k1 < 16; k1++) {
            const int s = ((k1 & 3) << 2) | (k1 >> 2);
            const float2 val = cmul(v[s], t);
            SRe[k1 * 68 + u] = val.x;
            SIm[k1 * 68 + u] = val.y;
            t = cmul(t, w);
        }
    }
    __syncthreads();

    // ---- stage B: FFT-16 over m1 (stride 4), in-place smem reuse ----
    const int k1 = u >> 2, m2 = u & 3;
#pragma unroll
    for (int m1 = 0; m1 < 16; m1++) {
        const int idx = k1 * 68 + 4 * m1 + m2;
        v[m1] = make_float2(SRe[idx], SIm[idx]);
    }
    __syncthreads();   // all reads done before overwriting buffer
    fft16(v);
    {   // twiddle W_64^{j1*m2} = (W_1024^{16*m2})^{j1}; write S2[j1*64 + k1*4 + m2]
        const float2 w = g_tw64[16 * m2];
        float2 t = w;
        SRe[k1 * 4 + m2] = v[0].x; SIm[k1 * 4 + m2] = v[0].y;
#pragma unroll
        for (int j1 = 1; j1 < 16; j1++) {
            const int s = ((j1 & 3) << 2) | (j1 >> 2);
            const float2 val = cmul(v[s], t);
            const int idx = j1 * 64 + k1 * 4 + m2;
            SRe[idx] = val.x;
            SIm[idx] = val.y;
            t = cmul(t, w);
        }
    }
    __syncthreads();

    // ---- stage C: radix-4 over m2, direct stores (k = kap, kap+256, [512]) ----
    const int jg = u & 3, k1c = u >> 2;
    float2* o2 = (float2*)out;
    const size_t obase = ((size_t)b * NBINS) * FRAMES + f;
#pragma unroll
    for (int dj = 0; dj < 4; dj++) {
        float2 d[4];
#pragma unroll
        for (int dm = 0; dm < 4; dm++) {        // rotated m2 -> conflict-free
            const int m2r = (jg + dm) & 3;
            const int idx = (4 * jg + dj) * 64 + k1c * 4 + m2r;
            d[m2r] = make_float2(SRe[idx], SIm[idx]);
        }
        const float2 t0 = cadd(d[0], d[2]), t1 = csub(d[0], d[2]);
        const float2 t2 = cadd(d[1], d[3]), t3 = csub(d[1], d[3]);
        const float2 X0 = cadd(t0, t2);                            // j2 = 0
        const float2 X1 = make_float2(t1.x + t3.y, t1.y - t3.x);   // j2 = 1
        const int kap = k1c + 64 * jg + 16 * dj;                   // < 256
        if (fv) {
            o2[obase + (size_t)kap * FRAMES]         = X0;
            o2[obase + (size_t)(kap + 256) * FRAMES] = X1;
            if (kap == 0)
                o2[obase + (size_t)512 * FRAMES] = csub(t0, t2);   // bin 512
        }
    }
}

extern "C" void kernel_launch(void* const* d_in, const int* in_sizes, int n_in,
                              void* d_out, int out_size) {
    const float* x = (const float*)d_in[0];
    float* out     = (float*)d_out;

    table_kernel<<<17, 64>>>();

    const int smem_bytes = FG * 2176 * sizeof(float);   // 34816
    cudaFuncSetAttribute(stft_fft_kernel,
                         cudaFuncAttributeMaxDynamicSharedMemorySize, smem_bytes);
    dim3 grid((FRAMES + FG - 1) / FG,   // 126
              NBATCH);                  // 32
    stft_fft_kernel<<<grid, 256, smem_bytes>>>(x, out);
}

// round 10
// speedup vs baseline: 6.5200x; 1.2722x over previous
#include <cuda_runtime.h>
#include <cstdint>
#include <math.h>

// ConvSTFT via windowed FFT-1024 = 16 x 16 x 4, register radix-16, with
// real-input packing: two frames per complex FFT (z = fa + i*fb), then
// Xa[k] = (Z[k]+conj(Z[N-k]))/2,  Xb[k] = (Z[k]-conj(Z[N-k]))/(2i).
// CTA: 8 frames = 4 packed FFTs, 64 threads each (256 threads).

#define TLEN   160000
#define NBATCH 32
#define FRAMES 501
#define NBINS  513
#define HOP    320
#define FPC    8                 // frames per CTA
#define PBLK   2184              // floats per packed-FFT block (mod 32 == 8)
#define IMOFF  1088

__device__ float  g_win[1024];
__device__ float2 g_tw64[64];    // W_1024^e = e^{-2pi i e/1024}, e < 64

__global__ void table_kernel() {
    int id = blockIdx.x * 64 + threadIdx.x;
    if (id < 1024) {
        double w = 0.0;
        if (id >= 112 && id < 912)
            w = 0.5 * (1.0 - cos(2.0 * M_PI * (double)(id - 112) / 799.0));
        g_win[id] = (float)w;
    } else if (id < 1088) {
        int e = id - 1024;
        double ang = 2.0 * M_PI * (double)e / 1024.0;
        g_tw64[e] = make_float2((float)cos(ang), (float)(-sin(ang)));
    }
}

__device__ __forceinline__ float2 cadd(float2 a, float2 b) {
    return make_float2(a.x + b.x, a.y + b.y);
}
__device__ __forceinline__ float2 csub(float2 a, float2 b) {
    return make_float2(a.x - b.x, a.y - b.y);
}
__device__ __forceinline__ float2 cmul(float2 a, float2 b) {
    return make_float2(a.x * b.x - a.y * b.y, a.x * b.y + a.y * b.x);
}
__device__ __forceinline__ void r4(float2& a, float2& b, float2& c, float2& d) {
    float2 t0 = cadd(a, c), t1 = csub(a, c), t2 = cadd(b, d), t3 = csub(b, d);
    a = cadd(t0, t2);
    b = make_float2(t1.x + t3.y, t1.y - t3.x);
    c = csub(t0, t2);
    d = make_float2(t1.x - t3.y, t1.y + t3.x);
}
// FFT-16 in regs; freq f lives at slot ((f&3)<<2) | (f>>2).
__device__ __forceinline__ void fft16(float2 v[16]) {
#pragma unroll
    for (int n2 = 0; n2 < 4; n2++) r4(v[n2], v[n2 + 4], v[n2 + 8], v[n2 + 12]);
    const float C8 = 0.70710678118654752f;
    const float c1 = 0.92387953251128674f, s1 = 0.38268343236508977f;
    const float2 W1 = make_float2(c1, -s1),  W2 = make_float2(C8, -C8);
    const float2 W3 = make_float2(s1, -c1),  W4 = make_float2(0.f, -1.f);
    const float2 W6 = make_float2(-C8, -C8), W9 = make_float2(-c1, s1);
    v[5]  = cmul(v[5],  W1); v[6]  = cmul(v[6],  W2); v[7]  = cmul(v[7],  W3);
    v[9]  = cmul(v[9],  W2); v[10] = cmul(v[10], W4); v[11] = cmul(v[11], W6);
    v[13] = cmul(v[13], W3); v[14] = cmul(v[14], W6); v[15] = cmul(v[15], W9);
#pragma unroll
    for (int k1 = 0; k1 < 4; k1++) r4(v[4*k1], v[4*k1+1], v[4*k1+2], v[4*k1+3]);
}
// storage permutation for stage-C results: bin -> smem slot
__device__ __forceinline__ int LOC(int k) {
    return (k & 15) | (((k >> 6) & 1) << 4) | (((k >> 7) & 1) << 5)
         | (((k >> 4) & 3) << 6) | (((k >> 8) & 3) << 8);
}

__global__ __launch_bounds__(256)
void stft_fft_kernel(const float* __restrict__ x, float* __restrict__ out) {
    extern __shared__ float smem[];   // [4 packed FFTs][PBLK]
    const int tid = threadIdx.x;
    const int g   = tid >> 6;         // packed-FFT index 0..3
    const int u   = tid & 63;         // thread within FFT (= n2)
    const int f0  = blockIdx.x * FPC;
    const int b   = blockIdx.y;
    float* SRe = smem + g * PBLK;
    float* SIm = SRe + IMOFF;
    const int fa = f0 + 2 * g, fb = fa + 1;
    const float* xrow = x + (size_t)b * TLEN;

    // ---- stage A: load two frames packed, FFT-16 over n1 (stride 64) ----
    float2 v[16];
#pragma unroll
    for (int n1 = 0; n1 < 16; n1++) {
        const int p   = n1 * 64 + u;
        const float w = g_win[p];
        const int xia = fa * HOP + p - 512;
        const int xib = xia + HOP;
        float ra = 0.f, rb = 0.f;
        if (fa < FRAMES && xia >= 0 && xia < TLEN) ra = xrow[xia] * w;
        if (fb < FRAMES && xib >= 0 && xib < TLEN) rb = xrow[xib] * w;
        v[n1] = make_float2(ra, rb);
    }
    fft16(v);
    {   // twiddle W_1024^{k1*u}; write S1[k1*68 + u]
        const float2 w = g_tw64[u];
        float2 t = w;
        SRe[u] = v[0].x; SIm[u] = v[0].y;
#pragma unroll
        for (int k1 = 1; k1 < 16; k1++) {
            const int s = ((k1 & 3) << 2) | (k1 >> 2);
            const float2 val = cmul(v[s], t);
            SRe[k1 * 68 + u] = val.x;
            SIm[k1 * 68 + u] = val.y;
            t = cmul(t, w);
        }
    }
    __syncthreads();

    // ---- stage B: FFT-16 over m1 (stride 4) ----
    const int k1 = u >> 2, m2 = u & 3;
#pragma unroll
    for (int m1 = 0; m1 < 16; m1++) {
        const int idx = k1 * 68 + 4 * m1 + m2;
        v[m1] = make_float2(SRe[idx], SIm[idx]);
    }
    __syncthreads();
    fft16(v);
    {   // twiddle W_64^{j1*m2}; write S2[j1*64 + k1*4 + m2]
        const float2 w = g_tw64[16 * m2];
        float2 t = w;
        SRe[k1 * 4 + m2] = v[0].x; SIm[k1 * 4 + m2] = v[0].y;
#pragma unroll
        for (int j1 = 1; j1 < 16; j1++) {
            const int s = ((j1 & 3) << 2) | (j1 >> 2);
            const float2 val = cmul(v[s], t);
            const int idx = j1 * 64 + k1 * 4 + m2;
            SRe[idx] = val.x;
            SIm[idx] = val.y;
            t = cmul(t, w);
        }
    }
    __syncthreads();

    // ---- stage C: radix-4 over m2; ALL 1024 bins to smem (permuted) ----
    const int jg = u & 3, k1c = u >> 2;     // k1c 0..15
    float2 d[4][4];
#pragma unroll
    for (int dj = 0; dj < 4; dj++)
#pragma unroll
        for (int dm = 0; dm < 4; dm++) {     // rotated m2 -> conflict-free
            const int m2r = (jg + dm) & 3;
            const int idx = (4 * jg + dj) * 64 + k1c * 4 + m2r;
            d[dj][m2r] = make_float2(SRe[idx], SIm[idx]);
        }
    __syncthreads();   // all reads done before overwriting buffer
    const int locbase = k1c | ((jg & 1) << 4) | ((jg >> 1) << 5);
#pragma unroll
    for (int dj = 0; dj < 4; dj++) {
        float2 X[4];
        X[0] = d[dj][0]; X[1] = d[dj][1]; X[2] = d[dj][2]; X[3] = d[dj][3];
        r4(X[0], X[1], X[2], X[3]);         // bins kap + 256*j2
#pragma unroll
        for (int j2 = 0; j2 < 4; j2++) {
            const int loc = locbase + (dj << 6) + (j2 << 8);
            SRe[loc] = X[j2].x;
            SIm[loc] = X[j2].y;
        }
    }
    __syncthreads();

    // ---- unpack + coalesced store: (k, p) pairs, 64B runs per bin ----
    float2* o2 = (float2*)out;
#pragma unroll
    for (int it = 0; it < 9; it++) {
        const int idx = tid + 256 * it;
        if (idx >= NBINS * 4) break;
        const int k  = idx >> 2;
        const int p  = idx & 3;
        const int kb = (1024 - k) & 1023;
        const float* Re = smem + p * PBLK;
        const float* Im = Re + IMOFF;
        const int l1 = LOC(k), l2 = LOC(kb);
        const float zr1 = Re[l1], zi1 = Im[l1];
        const float zr2 = Re[l2], zi2 = Im[l2];
        const float2 Xa = make_float2(0.5f * (zr1 + zr2), 0.5f * (zi1 - zi2));
        const float2 Xb = make_float2(0.5f * (zi1 + zi2), 0.5f * (zr2 - zr1));
        const int ffa = f0 + 2 * p;
        const size_t base = ((size_t)b * NBINS + k) * FRAMES + ffa;
        if (ffa < FRAMES)     o2[base]     = Xa;
        if (ffa + 1 < FRAMES) o2[base + 1] = Xb;
    }
}

extern "C" void kernel_launch(void* const* d_in, const int* in_sizes, int n_in,
                              void* d_out, int out_size) {
    const float* x = (const float*)d_in[0];
    float* out     = (float*)d_out;

    table_kernel<<<17, 64>>>();

    const int smem_bytes = 4 * PBLK * sizeof(float);   // 34944
    cudaFuncSetAttribute(stft_fft_kernel,
                         cudaFuncAttributeMaxDynamicSharedMemorySize, smem_bytes);
    dim3 grid((FRAMES + FPC - 1) / FPC,   // 63
              NBATCH);                    // 32
    stft_fft_kernel<<<grid, 256, smem_bytes>>>(x, out);
}

// round 11
// speedup vs baseline: 7.7528x; 1.1891x over previous
#include <cuda_runtime.h>
#include <cstdint>
#include <math.h>

// ConvSTFT via windowed FFT-1024 = 16 x 16 x 4, register radix-16,
// real-input packing (two frames per complex FFT), AoS float2 smem.
// CTA: 8 frames = 4 packed FFTs, 64 threads each (256 threads).

#define TLEN   160000
#define NBATCH 32
#define FRAMES 501
#define NBINS  513
#define HOP    320
#define FPC    8
#define PBLK2  1092              // float2 per packed-FFT block (2*1092 mod 32 == 8)

__device__ float  g_win[1024];
__device__ float2 g_tw64[64];    // W_1024^e = e^{-2pi i e/1024}

__global__ void table_kernel() {
    int id = blockIdx.x * 64 + threadIdx.x;
    if (id < 1024) {
        double w = 0.0;
        if (id >= 112 && id < 912)
            w = 0.5 * (1.0 - cos(2.0 * M_PI * (double)(id - 112) / 799.0));
        g_win[id] = (float)w;
    } else if (id < 1088) {
        int e = id - 1024;
        double ang = 2.0 * M_PI * (double)e / 1024.0;
        g_tw64[e] = make_float2((float)cos(ang), (float)(-sin(ang)));
    }
}

__device__ __forceinline__ float2 cadd(float2 a, float2 b) {
    return make_float2(a.x + b.x, a.y + b.y);
}
__device__ __forceinline__ float2 csub(float2 a, float2 b) {
    return make_float2(a.x - b.x, a.y - b.y);
}
__device__ __forceinline__ float2 cmul(float2 a, float2 b) {
    return make_float2(a.x * b.x - a.y * b.y, a.x * b.y + a.y * b.x);
}
__device__ __forceinline__ void r4(float2& a, float2& b, float2& c, float2& d) {
    float2 t0 = cadd(a, c), t1 = csub(a, c), t2 = cadd(b, d), t3 = csub(b, d);
    a = cadd(t0, t2);
    b = make_float2(t1.x + t3.y, t1.y - t3.x);
    c = csub(t0, t2);
    d = make_float2(t1.x - t3.y, t1.y + t3.x);
}
// FFT-16 in regs; freq f lives at slot ((f&3)<<2) | (f>>2).
__device__ __forceinline__ void fft16(float2 v[16]) {
#pragma unroll
    for (int n2 = 0; n2 < 4; n2++) r4(v[n2], v[n2 + 4], v[n2 + 8], v[n2 + 12]);
    const float C8 = 0.70710678118654752f;
    const float c1 = 0.92387953251128674f, s1 = 0.38268343236508977f;
    const float2 W1 = make_float2(c1, -s1),  W2 = make_float2(C8, -C8);
    const float2 W3 = make_float2(s1, -c1),  W4 = make_float2(0.f, -1.f);
    const float2 W6 = make_float2(-C8, -C8), W9 = make_float2(-c1, s1);
    v[5]  = cmul(v[5],  W1); v[6]  = cmul(v[6],  W2); v[7]  = cmul(v[7],  W3);
    v[9]  = cmul(v[9],  W2); v[10] = cmul(v[10], W4); v[11] = cmul(v[11], W6);
    v[13] = cmul(v[13], W3); v[14] = cmul(v[14], W6); v[15] = cmul(v[15], W9);
#pragma unroll
    for (int k1 = 0; k1 < 4; k1++) r4(v[4*k1], v[4*k1+1], v[4*k1+2], v[4*k1+3]);
}
// bin k -> smem slot (stage-C storage permutation, XOR-swizzled for banks)
__device__ __forceinline__ int LOC(int k) {
    const int jg = (k >> 6) & 3;
    return ((k & 15) ^ (jg << 2)) | (jg << 4)
         | (((k >> 4) & 3) << 6) | (((k >> 8) & 3) << 8);
}

__global__ __launch_bounds__(256)
void stft_fft_kernel(const float* __restrict__ x, float* __restrict__ out) {
    extern __shared__ float2 smem[];   // [4][PBLK2]
    const int tid = threadIdx.x;
    const int g   = tid >> 6;          // packed-FFT index 0..3
    const int u   = tid & 63;          // thread within FFT (= n2)
    const int f0  = blockIdx.x * FPC;
    const int b   = blockIdx.y;
    float2* S = smem + g * PBLK2;
    const int fa = f0 + 2 * g, fb = fa + 1;
    const float* xrow = x + (size_t)b * TLEN;
    const bool interior = (blockIdx.x >= 1) && (blockIdx.x <= 61);

    // ---- stage A: load two frames packed, FFT-16 over n1 (stride 64) ----
    float2 v[16];
    if (interior) {
        const float* pa = xrow + fa * HOP - 512 + u;
#pragma unroll
        for (int n1 = 0; n1 < 16; n1++) {
            const float w = g_win[n1 * 64 + u];
            v[n1] = make_float2(pa[n1 * 64] * w, pa[n1 * 64 + HOP] * w);
        }
    } else {
#pragma unroll
        for (int n1 = 0; n1 < 16; n1++) {
            const int p   = n1 * 64 + u;
            const float w = g_win[p];
            const int xia = fa * HOP + p - 512;
            const int xib = xia + HOP;
            float ra = 0.f, rb = 0.f;
            if (fa < FRAMES && xia >= 0 && xia < TLEN) ra = xrow[xia] * w;
            if (fb < FRAMES && xib >= 0 && xib < TLEN) rb = xrow[xib] * w;
            v[n1] = make_float2(ra, rb);
        }
    }
    fft16(v);
    {   // twiddle W_1024^{k1*u}; write S[k1*68 + u]
        const float2 w = g_tw64[u];
        float2 t = w;
        S[u] = v[0];
#pragma unroll
        for (int k1 = 1; k1 < 16; k1++) {
            const int s = ((k1 & 3) << 2) | (k1 >> 2);
            S[k1 * 68 + u] = cmul(v[s], t);
            t = cmul(t, w);
        }
    }
    __syncthreads();

    // ---- stage B: FFT-16 over m1 (stride 4) ----
    const int k1 = u >> 2, m2 = u & 3;
#pragma unroll
    for (int m1 = 0; m1 < 16; m1++)
        v[m1] = S[k1 * 68 + 4 * m1 + m2];
    __syncthreads();
    fft16(v);
    {   // twiddle W_64^{j1*m2}; write S[j1*64 + k1*4 + m2]
        const float2 w = g_tw64[16 * m2];
        float2 t = w;
        S[k1 * 4 + m2] = v[0];
#pragma unroll
        for (int j1 = 1; j1 < 16; j1++) {
            const int s = ((j1 & 3) << 2) | (j1 >> 2);
            S[j1 * 64 + k1 * 4 + m2] = cmul(v[s], t);
            t = cmul(t, w);
        }
    }
    __syncthreads();

    // ---- stage C: radix-4 over m2; all 1024 bins to smem (permuted) ----
    const int jg = u & 3, k1c = u >> 2;
    float2 d[4][4];
#pragma unroll
    for (int dj = 0; dj < 4; dj++)
#pragma unroll
        for (int dm = 0; dm < 4; dm++) {     // rotated m2 -> conflict-free
            const int m2r = (jg + dm) & 3;
            d[dj][m2r] = S[(4 * jg + dj) * 64 + k1c * 4 + m2r];
        }
    __syncthreads();
    const int locbase = (k1c ^ (jg << 2)) | (jg << 4);
#pragma unroll
    for (int dj = 0; dj < 4; dj++) {
        r4(d[dj][0], d[dj][1], d[dj][2], d[dj][3]);   // bins kap + 256*j2
#pragma unroll
        for (int j2 = 0; j2 < 4; j2++)
            S[locbase + (dj << 6) + (j2 << 8)] = d[dj][j2];
    }
    __syncthreads();

    // ---- unpack + coalesced store: (k, p) pairs, 64B runs per bin ----
    float2* o2 = (float2*)out;
#pragma unroll
    for (int it = 0; it < 9; it++) {
        const int idx = tid + 256 * it;
        if (idx >= NBINS * 4) break;
        const int k  = idx >> 2;
        const int p  = idx & 3;
        const int kb = (1024 - k) & 1023;
        const float2 z1 = smem[p * PBLK2 + LOC(k)];
        const float2 z2 = smem[p * PBLK2 + LOC(kb)];
        const float2 Xa = make_float2(0.5f * (z1.x + z2.x), 0.5f * (z1.y - z2.y));
        const float2 Xb = make_float2(0.5f * (z1.y + z2.y), 0.5f * (z2.x - z1.x));
        const int ffa = f0 + 2 * p;
        const size_t base = ((size_t)b * NBINS + k) * FRAMES + ffa;
        if (interior) {
            o2[base]     = Xa;
            o2[base + 1] = Xb;
        } else {
            if (ffa < FRAMES)     o2[base]     = Xa;
            if (ffa + 1 < FRAMES) o2[base + 1] = Xb;
        }
    }
}

extern "C" void kernel_launch(void* const* d_in, const int* in_sizes, int n_in,
                              void* d_out, int out_size) {
    const float* x = (const float*)d_in[0];
    float* out     = (float*)d_out;

    table_kernel<<<17, 64>>>();

    const int smem_bytes = 4 * PBLK2 * sizeof(float2);   // 34944
    cudaFuncSetAttribute(stft_fft_kernel,
                         cudaFuncAttributeMaxDynamicSharedMemorySize, smem_bytes);
    dim3 grid((FRAMES + FPC - 1) / FPC,   // 63
              NBATCH);                    // 32
    stft_fft_kernel<<<grid, 256, smem_bytes>>>(x, out);
}